// round 14
// baseline (speedup 1.0000x reference)
#include <cuda_runtime.h>
#include <cstdint>

#define NB    8
#define CDIM  64
#define HH    256
#define WW    256
#define EPSV  1e-5f
#define RPC   32                 // rows per CTA tile
#define CPP   (HH / RPC)         // CTAs per plane = 8
#define GATE  (CDIM * CPP)       // CTAs per sample = 512
#define W4    (WW / 4)           // 64 float4 per row

// scratch (allocation-free rule: device globals)
__device__ float g_part[NB * CDIM * CPP];   // per-CTA partial plane sums
__device__ int   g_cnt[NB];                 // per-sample arrival counters

__global__ void init_kernel() {
    if (threadIdx.x < NB) g_cnt[threadIdx.x] = 0;
}

// One kernel: stage tile in smem -> partial GAP -> per-sample gate -> taps -> conv.
// x is read from DRAM exactly once (plus 2 halo rows per tile).
__global__ void __launch_bounds__(256) fused_kernel(
        const float* __restrict__ x, float* __restrict__ out,
        const float* __restrict__ wH, const float* __restrict__ gH,
        const float* __restrict__ bH, const float* __restrict__ mH,
        const float* __restrict__ vH,
        const float* __restrict__ wW, const float* __restrict__ gW,
        const float* __restrict__ bW, const float* __restrict__ mW,
        const float* __restrict__ vW) {
    __shared__ float sm[(RPC + 2) * WW];     // 34 KB tile (+1 halo row each side)
    __shared__ float sgap[CDIM];
    __shared__ float staps[6];
    __shared__ float red[8];

    int bid   = blockIdx.x;
    int plane = bid >> 3;                    // bid / CPP
    int seg   = bid & (CPP - 1);
    int n     = plane >> 6;
    int cch   = plane & 63;
    int h0    = seg * RPC;
    int t     = threadIdx.x;
    int g     = t & 63;
    int lane  = t & 31;

    const float4* xp4 = (const float4*)(x + (size_t)plane * HH * WW);

    // ---- phase 1: stage tile + partial sum ----
    float s = 0.f;
    #pragma unroll
    for (int i = 0; i < RPC * W4 / 256; i++) {        // 8 iters
        int idx = t + i * 256;
        int r = idx >> 6, q = idx & 63;
        float4 v = xp4[(h0 + r) * W4 + q];
        ((float4*)sm)[(r + 1) * W4 + q] = v;
        s += (v.x + v.y) + (v.z + v.w);
    }
    if (t < 2 * W4) {                                 // halo rows (reflect at edges)
        int which = t >> 6, q = t & 63;
        int gh = which ? (h0 + RPC > HH - 1 ? HH - 2 : h0 + RPC)
                       : (h0 == 0 ? 1 : h0 - 1);
        ((float4*)sm)[which * (RPC + 1) * W4 + q] = xp4[gh * W4 + q];
    }
    // block reduce partial sum
    #pragma unroll
    for (int o = 16; o > 0; o >>= 1)
        s += __shfl_down_sync(0xFFFFFFFFu, s, o);
    if (lane == 0) red[t >> 5] = s;
    __syncthreads();
    if (t == 0) {
        float p = red[0];
        #pragma unroll
        for (int w = 1; w < 8; w++) p += red[w];
        g_part[bid] = p;
        __threadfence();
        atomicAdd(&g_cnt[n], 1);
        // ---- gate: wait for all 512 CTAs of this sample ----
        volatile int* c = &g_cnt[n];
        while (*c < GATE) __nanosleep(64);
        __threadfence();
    }
    __syncthreads();

    // ---- gap vector (fixed summation order => deterministic) ----
    if (t < CDIM) {
        const float* pp = &g_part[(n * CDIM + t) * CPP];
        float a = 0.f;
        #pragma unroll
        for (int q = 0; q < CPP; q++) a += __ldcg(pp + q);   // bypass stale L1
        sgap[t] = a * (1.0f / (HH * WW));
    }
    __syncthreads();

    // ---- taps: tanh(BN(gap @ w^T)) for this plane's 6 taps ----
    if (t < 6) {
        int branch = t / 3;
        int k = t - branch * 3;
        int row = cch * 3 + k;
        const float* w  = branch ? wW : wH;
        const float* gg = branch ? gW : gH;
        const float* bb = branch ? bW : bH;
        const float* mm = branch ? mW : mH;
        const float* vv = branch ? vW : vH;
        const float* wr = w + row * CDIM;
        float d = 0.f;
        #pragma unroll
        for (int c = 0; c < CDIM; c++) d += sgap[c] * wr[c];
        float f = (d - mm[row]) * (gg[row] * rsqrtf(vv[row] + EPSV)) + bb[row];
        staps[t] = tanhf(f);
    }
    __syncthreads();

    float fh0 = staps[0], fh1 = staps[1], fh2 = staps[2];
    float fw0 = staps[3], fw1 = staps[4], fw2 = staps[5];

    // ---- phase 2: conv from smem ----
    float4* o1 = (float4*)(out + ((size_t)n * 2 * CDIM + cch) * HH * WW)
                 + (size_t)h0 * W4;
    float4* o2 = o1 + (size_t)CDIM * HH * WW / 4;

    int rbase = (t >> 6) * (RPC / 4);        // 4 chunks of 8 rows
    #pragma unroll
    for (int rr = 0; rr < RPC / 4; rr++) {
        int hl = rbase + rr;                 // local row 0..31
        const float4* ru = (const float4*)(sm + hl * WW);
        const float4* rc = (const float4*)(sm + (hl + 1) * WW);
        const float4* rd = (const float4*)(sm + (hl + 2) * WW);
        float4 up = ru[g], ce = rc[g], dn = rd[g];

        // horizontal halo: neighbor lanes' registers; warp-edge lanes hit smem
        float xl = __shfl_up_sync(0xFFFFFFFFu, ce.w, 1);
        float xr = __shfl_down_sync(0xFFFFFFFFu, ce.x, 1);
        if (lane == 0)
            xl = (g == 0)  ? ce.y : sm[(hl + 1) * WW + 4 * g - 1];
        if (lane == 31)
            xr = (g == 63) ? ce.z : sm[(hl + 1) * WW + 4 * g + 4];

        float4 h4;
        h4.x = fh0 * xl   + fh1 * ce.x + fh2 * ce.y;
        h4.y = fh0 * ce.x + fh1 * ce.y + fh2 * ce.z;
        h4.z = fh0 * ce.y + fh1 * ce.z + fh2 * ce.w;
        h4.w = fh0 * ce.z + fh1 * ce.w + fh2 * xr;
        float4 v4;
        v4.x = fw0 * up.x + fw1 * ce.x + fw2 * dn.x;
        v4.y = fw0 * up.y + fw1 * ce.y + fw2 * dn.y;
        v4.z = fw0 * up.z + fw1 * ce.z + fw2 * dn.z;
        v4.w = fw0 * up.w + fw1 * ce.w + fw2 * dn.w;

        __stcs(&o1[hl * W4 + g], h4);
        __stcs(&o2[hl * W4 + g], v4);
    }
}

extern "C" void kernel_launch(void* const* d_in, const int* in_sizes, int n_in,
                              void* d_out, int out_size) {
    const float* x  = (const float*)d_in[0];
    const float* wH = (const float*)d_in[1];
    const float* gH = (const float*)d_in[2];
    const float* bH = (const float*)d_in[3];
    const float* mH = (const float*)d_in[4];
    const float* vH = (const float*)d_in[5];
    const float* wW = (const float*)d_in[6];
    const float* gW = (const float*)d_in[7];
    const float* bW = (const float*)d_in[8];
    const float* mW = (const float*)d_in[9];
    const float* vW = (const float*)d_in[10];
    float* out = (float*)d_out;

    init_kernel<<<1, 32>>>();
    fused_kernel<<<NB * CDIM * CPP, 256>>>(x, out, wH, gH, bH, mH, vH,
                                           wW, gW, bW, mW, vW);
}

// round 15
// speedup vs baseline: 1.3922x; 1.3922x over previous
#include <cuda_runtime.h>
#include <cstdint>

#define NB    8
#define CDIM  64
#define HH    256
#define WW    256
#define EPSV  1e-5f
#define RPT   16                 // rows per thread in conv
#define CPP   8                  // partial-sum CTAs per plane
#define W4    (WW / 4)

// scratch (allocation-free rule: device globals)
__device__ float g_part[NB * CDIM * CPP];   // per-CTA partial plane sums

// ---------------- Kernel 1: fine-grained partial plane sums ----------------
// 4096 CTAs x 256 threads; each CTA sums 32 rows of one plane (8 float4/thread).
__global__ void __launch_bounds__(256) part_kernel(const float* __restrict__ x) {
    int bid   = blockIdx.x;                  // 0..4095
    int plane = bid >> 3;
    int seg   = bid & (CPP - 1);
    const float4* p = (const float4*)(x + (size_t)plane * HH * WW) + seg * (HH / CPP) * W4;
    float s = 0.f;
    #pragma unroll
    for (int j = 0; j < (HH / CPP) * W4 / 256; j++) {   // 8 iterations, full MLP
        float4 v = p[threadIdx.x + j * 256];
        s += (v.x + v.y) + (v.z + v.w);
    }
    #pragma unroll
    for (int o = 16; o > 0; o >>= 1)
        s += __shfl_down_sync(0xFFFFFFFFu, s, o);
    __shared__ float red[8];
    if ((threadIdx.x & 31) == 0) red[threadIdx.x >> 5] = s;
    __syncthreads();
    if (threadIdx.x == 0) {
        float t = red[0];
        #pragma unroll
        for (int w = 1; w < 8; w++) t += red[w];
        g_part[bid] = t;
    }
}

// ---------------- Kernel 2: fused gap-reduce + taps + strip conv ----------------
// grid = 2048 blocks (4 per (n,c) plane), 256 threads, reverse plane order.
__global__ void __launch_bounds__(256, 6) conv_kernel(
        const float* __restrict__ x, float* __restrict__ out,
        const float* __restrict__ wH, const float* __restrict__ gH,
        const float* __restrict__ bH, const float* __restrict__ mH,
        const float* __restrict__ vH,
        const float* __restrict__ wW, const float* __restrict__ gW,
        const float* __restrict__ bW, const float* __restrict__ mW,
        const float* __restrict__ vW) {
    int plane = (NB * CDIM - 1) - (blockIdx.x >> 2);   // 511..0 (reverse)
    int quart = blockIdx.x & 3;
    int n   = plane >> 6;
    int cch = plane & 63;
    int t = threadIdx.x;
    int g = t & 63;
    int h0 = quart * 64 + (t >> 6) * RPT;

    __shared__ float sgap[CDIM];
    __shared__ float taps[6];

    // gap vector: fixed-order 8-way reduction of partials (deterministic, L2-hot)
    if (t < CDIM) {
        const float* pp = &g_part[(n * CDIM + t) * CPP];
        float a = 0.f;
        #pragma unroll
        for (int q = 0; q < CPP; q++) a += pp[q];
        sgap[t] = a * (1.0f / (HH * WW));
    }
    __syncthreads();

    if (t < 6) {
        int branch = t / 3;              // 0=H, 1=W
        int k = t - branch * 3;
        int row = cch * 3 + k;
        const float* w  = branch ? wW : wH;
        const float* gg = branch ? gW : gH;
        const float* bb = branch ? bW : bH;
        const float* mm = branch ? mW : mH;
        const float* vv = branch ? vW : vH;
        const float* wr = w + row * CDIM;
        float s = 0.f;
        #pragma unroll
        for (int c = 0; c < CDIM; c++) s += sgap[c] * wr[c];
        float f = (s - mm[row]) * (gg[row] * rsqrtf(vv[row] + EPSV)) + bb[row];
        taps[t] = tanhf(f);
    }
    __syncthreads();

    float fh0 = taps[0], fh1 = taps[1], fh2 = taps[2];
    float fw0 = taps[3], fw1 = taps[4], fw2 = taps[5];

    const float4* xp4 = (const float4*)(x + (size_t)plane * HH * WW);
    const float*  xp  = x + (size_t)plane * HH * WW;

    float4* o1 = (float4*)(out + ((size_t)n * 2 * CDIM + cch) * HH * WW);
    float4* o2 = o1 + (size_t)CDIM * HH * WW / 4;

    auto process = [&](int h, const float4& up, const float4& ce, const float4& dn) {
        float xl = (g == 0)  ? ce.y : xp[h * WW + 4 * g - 1];   // reflect left
        float xr = (g == 63) ? ce.z : xp[h * WW + 4 * g + 4];   // reflect right
        float4 h4;
        h4.x = fh0 * xl   + fh1 * ce.x + fh2 * ce.y;
        h4.y = fh0 * ce.x + fh1 * ce.y + fh2 * ce.z;
        h4.z = fh0 * ce.y + fh1 * ce.z + fh2 * ce.w;
        h4.w = fh0 * ce.z + fh1 * ce.w + fh2 * xr;
        float4 v4;
        v4.x = fw0 * up.x + fw1 * ce.x + fw2 * dn.x;
        v4.y = fw0 * up.y + fw1 * ce.y + fw2 * dn.y;
        v4.z = fw0 * up.z + fw1 * ce.z + fw2 * dn.z;
        v4.w = fw0 * up.w + fw1 * ce.w + fw2 * dn.w;
        __stcs(&o1[h * W4 + g], h4);     // streaming stores
        __stcs(&o2[h * W4 + g], v4);
    };

    // rolling window: u = row h-1, cc = row h
    int hu = (h0 == 0) ? 1 : h0 - 1;         // reflect top
    float4 u  = xp4[hu * W4 + g];
    float4 cc = xp4[h0 * W4 + g];

    #pragma unroll
    for (int hb = 0; hb < RPT; hb += 4) {
        int h = h0 + hb;
        int r1 = h + 1, r2 = h + 2, r3 = h + 3, r4 = h + 4;
        if (r4 > HH - 1) r4 = HH - 2;        // reflect bottom (only last batch)
        if (r3 > HH - 1) r3 = HH - 2;
        // 4 independent vector loads -> MLP 4
        float4 d0 = xp4[r1 * W4 + g];
        float4 d1 = xp4[r2 * W4 + g];
        float4 d2 = xp4[r3 * W4 + g];
        float4 d3 = xp4[r4 * W4 + g];

        process(h,     u,  cc, d0);
        process(h + 1, cc, d0, d1);
        process(h + 2, d0, d1, d2);
        process(h + 3, d1, d2, d3);

        u  = d2;
        cc = d3;
    }
}

extern "C" void kernel_launch(void* const* d_in, const int* in_sizes, int n_in,
                              void* d_out, int out_size) {
    const float* x  = (const float*)d_in[0];
    const float* wH = (const float*)d_in[1];
    const float* gH = (const float*)d_in[2];
    const float* bH = (const float*)d_in[3];
    const float* mH = (const float*)d_in[4];
    const float* vH = (const float*)d_in[5];
    const float* wW = (const float*)d_in[6];
    const float* gW = (const float*)d_in[7];
    const float* bW = (const float*)d_in[8];
    const float* mW = (const float*)d_in[9];
    const float* vW = (const float*)d_in[10];
    float* out = (float*)d_out;

    part_kernel<<<NB * CDIM * CPP, 256>>>(x);
    conv_kernel<<<4 * NB * CDIM, 256>>>(x, out, wH, gH, bH, mH, vH,
                                        wW, gW, bW, mW, vW);
}